// round 10
// baseline (speedup 1.0000x reference)
#include <cuda_runtime.h>
#include <cuda_fp16.h>
#include <math.h>
#include <stdint.h>

// ---------------- problem constants ----------------
#define S_LEN 128
#define BATCH 32
#define HID   1024
#define EMB   1024
#define VOCAB 32000
#define SB    (S_LEN * BATCH)          // 4096
#define BH    (BATCH * HID)            // 32768
#define NBLK  256                      // persistent recurrence grid

// ---------------- scratch (device globals; no runtime alloc) ----------------
__device__ float  g_embeds[SB * EMB];      // [S*B, E] exact fp32
__device__ __half g_embeds_h[SB * EMB];    // fp16 copy (GEMM A operand)
__device__ float  g_xi1[SB * HID];
__device__ float  g_xf1[SB * HID];
__device__ float  g_xi2[SB * HID];
__device__ float  g_xf2[SB * HID];
__device__ float  g_lats1[SB * HID];       // layer-1 latent sequence (= l1_out)
__device__ __half g_lats1_h[SB * HID];
__device__ float  g_lats2[SB * HID];       // layer-2 latent sequence (= l2_out)
__device__ __half g_lats2_h[SB * HID];
__device__ float  g_part0[8 * BH];         // split-K partials, gate i
__device__ float  g_part1[8 * BH];         // split-K partials, gate f
__device__ __half g_h2o_h[(size_t)VOCAB * HID];   // 64MB fp16 weight copy
__device__ __half g_wx_h[4][HID * EMB];           // fp16 copies of Wxi,Wxf,Wxi2,Wxf2
__device__ unsigned int g_bar_count;
__device__ unsigned int g_bar_gen;

// ---------------- helpers ----------------
__device__ __forceinline__ void mma_f16(float c[4],
                                        uint32_t a0, uint32_t a1, uint32_t a2, uint32_t a3,
                                        uint32_t b0, uint32_t b1) {
    asm volatile(
        "mma.sync.aligned.m16n8k16.row.col.f32.f16.f16.f32 "
        "{%0,%1,%2,%3}, {%4,%5,%6,%7}, {%8,%9}, {%0,%1,%2,%3};"
        : "+f"(c[0]), "+f"(c[1]), "+f"(c[2]), "+f"(c[3])
        : "r"(a0), "r"(a1), "r"(a2), "r"(a3), "r"(b0), "r"(b1));
}

__device__ __forceinline__ void cp_async16(void* smem_dst, const void* gsrc) {
    uint32_t s = (uint32_t)__cvta_generic_to_shared(smem_dst);
    asm volatile("cp.async.cg.shared.global [%0], [%1], 16;" :: "r"(s), "l"(gsrc));
}

// ---------------- fp16 conversion pre-pass ----------------
__global__ void to_f16_kernel(const float* __restrict__ src, __half* __restrict__ dst,
                              int n4) {
    int i = blockIdx.x * blockDim.x + threadIdx.x;
    if (i < n4) {
        float4 v = ((const float4*)src)[i];
        __half2* d = (__half2*)(dst + (size_t)i * 4);
        d[0] = __floats2half2_rn(v.x, v.y);
        d[1] = __floats2half2_rn(v.z, v.w);
    }
}

// ---------------- embedding gather (writes fp32 + fp16 copies) ----------------
__global__ void embed_gather(const int* __restrict__ word,
                             const float* __restrict__ emb,
                             float* __restrict__ out,
                             __half* __restrict__ out_h) {
    int row = blockIdx.x;                 // 0..4095 = s*B+b
    int w = word[row];
    float4 v = ((const float4*)(emb + (size_t)w * EMB))[threadIdx.x];
    ((float4*)(out + (size_t)row * EMB))[threadIdx.x] = v;
    __half2* d = (__half2*)(out_h + (size_t)row * EMB + (size_t)threadIdx.x * 4);
    d[0] = __floats2half2_rn(v.x, v.y);
    d[1] = __floats2half2_rn(v.z, v.w);
}

// ---------------- pipelined fp16 NT GEMM: C = A[M,K]*B[N,K]^T + bias[N] ------
// A,B fp16 (pre-converted), fp32 accum. BM=BN=128, BK=32, 3-stage cp.async,
// ldmatrix fragment loads + mma.sync m16n8k16. 8 warps (4m x 2n), warp 32x64.
#define PSTAGES 3
#define HSTRIDE 40                       // halves per tile row (32 data + 8 pad)
#define HTILE   (128 * HSTRIDE)          // 5120 halves per tile
#define GEMM_SMEM (PSTAGES * 2 * HTILE * 2)   // 61440 bytes

__global__ __launch_bounds__(256, 2)
void gemm_f16_pipe(const __half* __restrict__ A, const __half* __restrict__ B,
                   const float* __restrict__ bias, float* __restrict__ C,
                   int M, int N, int K, int swap) {
    extern __shared__ __half smh[];
    __half* As = smh;                      // [PSTAGES][128][HSTRIDE]
    __half* Bs = smh + PSTAGES * HTILE;

    int tid = threadIdx.x;
    int bn = (swap ? blockIdx.y : blockIdx.x) * 128;
    int bm = (swap ? blockIdx.x : blockIdx.y) * 128;
    int wid = tid >> 5, lane = tid & 31;
    int wm = wid & 3;
    int wn = wid >> 2;
    int grp = lane >> 2;
    int tig = lane & 3;
    int mat = lane >> 3;                   // ldmatrix matrix selector 0..3
    int lrow = lane & 7;                   // ldmatrix row-within-matrix

    // load mapping: tile = 128 rows x 32 halves = 512 16B-chunks; thread does 2
    int r0 = tid >> 2, c0 = (tid & 3) << 3;      // chunk tid
    int r1 = r0 + 64, c1 = c0;                   // chunk tid+256
    const __half* Ab = A + (size_t)bm * K;
    const __half* Bb = B + (size_t)bn * K;

    float acc[2][8][4];
#pragma unroll
    for (int i = 0; i < 2; i++)
#pragma unroll
        for (int j = 0; j < 8; j++)
#pragma unroll
            for (int q = 0; q < 4; q++) acc[i][j][q] = 0.f;

    int KT = K >> 5;

#pragma unroll
    for (int s = 0; s < PSTAGES - 1; s++) {
        int k0 = s * 32;
        cp_async16(&As[s * HTILE + r0 * HSTRIDE + c0], Ab + (size_t)r0 * K + k0 + c0);
        cp_async16(&As[s * HTILE + r1 * HSTRIDE + c1], Ab + (size_t)r1 * K + k0 + c1);
        cp_async16(&Bs[s * HTILE + r0 * HSTRIDE + c0], Bb + (size_t)r0 * K + k0 + c0);
        cp_async16(&Bs[s * HTILE + r1 * HSTRIDE + c1], Bb + (size_t)r1 * K + k0 + c1);
        asm volatile("cp.async.commit_group;");
    }

    for (int kt = 0; kt < KT; kt++) {
        asm volatile("cp.async.wait_group %0;" :: "n"(PSTAGES - 2));
        __syncthreads();

        const __half* Ast = &As[(kt % PSTAGES) * HTILE];
        const __half* Bst = &Bs[(kt % PSTAGES) * HTILE];

#pragma unroll
        for (int ks = 0; ks < 2; ks++) {
            int kb0 = ks * 16;
            // A fragments: 2x ldmatrix.x4 (16x16 tiles at rows wm*32+i*16)
            uint32_t af[2][4];
#pragma unroll
            for (int i = 0; i < 2; i++) {
                int row = wm * 32 + i * 16 + ((mat & 1) << 3) + lrow;
                int kk = kb0 + ((mat >> 1) << 3);
                uint32_t a = (uint32_t)__cvta_generic_to_shared(&Ast[row * HSTRIDE + kk]);
                asm volatile(
                    "ldmatrix.sync.aligned.m8n8.x4.shared.b16 {%0,%1,%2,%3}, [%4];"
                    : "=r"(af[i][0]), "=r"(af[i][1]), "=r"(af[i][2]), "=r"(af[i][3])
                    : "r"(a));
            }
            // B fragments: 4x ldmatrix.x4 (each covers 2 n-octets x 2 k-halves)
            uint32_t bf[8][2];
#pragma unroll
            for (int jj = 0; jj < 4; jj++) {
                int j = 2 * jj + (mat >> 1);
                int row = wn * 64 + j * 8 + lrow;
                int kk = kb0 + ((mat & 1) << 3);
                uint32_t a = (uint32_t)__cvta_generic_to_shared(&Bst[row * HSTRIDE + kk]);
                asm volatile(
                    "ldmatrix.sync.aligned.m8n8.x4.shared.b16 {%0,%1,%2,%3}, [%4];"
                    : "=r"(bf[2 * jj][0]), "=r"(bf[2 * jj][1]),
                      "=r"(bf[2 * jj + 1][0]), "=r"(bf[2 * jj + 1][1])
                    : "r"(a));
            }
#pragma unroll
            for (int i = 0; i < 2; i++)
#pragma unroll
                for (int j = 0; j < 8; j++)
                    mma_f16(acc[i][j], af[i][0], af[i][1], af[i][2], af[i][3],
                            bf[j][0], bf[j][1]);
        }

        int nk = kt + PSTAGES - 1;
        if (nk < KT) {
            int st = nk % PSTAGES;
            int k0 = nk * 32;
            cp_async16(&As[st * HTILE + r0 * HSTRIDE + c0], Ab + (size_t)r0 * K + k0 + c0);
            cp_async16(&As[st * HTILE + r1 * HSTRIDE + c1], Ab + (size_t)r1 * K + k0 + c1);
            cp_async16(&Bs[st * HTILE + r0 * HSTRIDE + c0], Bb + (size_t)r0 * K + k0 + c0);
            cp_async16(&Bs[st * HTILE + r1 * HSTRIDE + c1], Bb + (size_t)r1 * K + k0 + c1);
        }
        asm volatile("cp.async.commit_group;");
    }

    // epilogue (fp32 accumulators + bias)
#pragma unroll
    for (int i = 0; i < 2; i++) {
        int row = bm + wm * 32 + i * 16 + grp;
#pragma unroll
        for (int j = 0; j < 8; j++) {
            int col = bn + wn * 64 + j * 8 + 2 * tig;
            float bsv0 = bias[col], bsv1 = bias[col + 1];
            float2 o0 = make_float2(acc[i][j][0] + bsv0, acc[i][j][1] + bsv1);
            float2 o1 = make_float2(acc[i][j][2] + bsv0, acc[i][j][3] + bsv1);
            *(float2*)(C + (size_t)row * N + col) = o0;
            *(float2*)(C + (size_t)(row + 8) * N + col) = o1;
        }
    }
}

// ---------------- software grid barrier (all NBLK blocks co-resident) --------
__device__ __forceinline__ void grid_barrier() {
    __syncthreads();
    if (threadIdx.x == 0) {
        volatile unsigned int* genp = &g_bar_gen;
        unsigned int gen = *genp;
        __threadfence();
        unsigned int rank = atomicAdd(&g_bar_count, 1u);
        if (rank == NBLK - 1) {
            g_bar_count = 0u;
            __threadfence();
            *genp = gen + 1u;
        } else {
            while (*genp == gen) { __nanosleep(32); }
        }
        __threadfence();
    }
    __syncthreads();
}

// ---------------- persistent recurrence (R4-proven): one launch per layer ----
__global__ __launch_bounds__(256)
void ran_recurrence(const float* __restrict__ Wi, const float* __restrict__ Wf,
                    const float* __restrict__ xi, const float* __restrict__ xf,
                    const float* __restrict__ xseq,
                    const float* __restrict__ lat0,
                    float* __restrict__ lats,
                    __half* __restrict__ lats_h,      // fp16 copy for GEMMs
                    float* __restrict__ part0, float* __restrict__ part1,
                    float* __restrict__ igout, float* __restrict__ fgout) {
    extern __shared__ char smem_raw[];
    float (*sW)[32][128] = (float (*)[32][128])smem_raw;
    float4 (*sLat)[33] = (float4 (*)[33])(smem_raw + 2 * 32 * 128 * 4);

    int tid = threadIdx.x;
    int gt = blockIdx.x & 31;
    int kc = blockIdx.x >> 5;
    int g0 = gt * 32;
    int k0 = kc * 128;

    for (int i = tid; i < 2048; i += 256) {
        int mtx = i >> 10;
        int g = (i >> 5) & 31, kq = i & 31;
        const float* Wp = mtx ? Wf : Wi;
        *(float4*)&sW[mtx][g][kq * 4] =
            *(const float4*)(Wp + (size_t)(g0 + g) * HID + k0 + kq * 4);
    }

    int w = tid >> 5, lane = tid & 31;

    for (int s = 0; s < S_LEN; s++) {
        const float* latp = (s == 0) ? lat0 : (lats + (size_t)(s - 1) * BH);

        for (int i = tid; i < 1024; i += 256) {
            int b = i >> 5, kq = i & 31;
            const float4* src = (const float4*)(latp + b * HID + k0 + kq * 4);
            sLat[b][kq] = __ldcg(src);
        }
        __syncthreads();

        float ai[4] = {0.f, 0.f, 0.f, 0.f};
        float af[4] = {0.f, 0.f, 0.f, 0.f};
#pragma unroll 8
        for (int k4 = 0; k4 < 32; k4++) {
            float4 lv = sLat[lane][k4];
#pragma unroll
            for (int j = 0; j < 4; j++) {
                float4 wiv = *(const float4*)&sW[0][w * 4 + j][k4 * 4];
                float4 wfv = *(const float4*)&sW[1][w * 4 + j][k4 * 4];
                ai[j] += wiv.x * lv.x + wiv.y * lv.y + wiv.z * lv.z + wiv.w * lv.w;
                af[j] += wfv.x * lv.x + wfv.y * lv.y + wfv.z * lv.z + wfv.w * lv.w;
            }
        }
        int base = kc * BH + (g0 + w * 4) * 32 + lane;
#pragma unroll
        for (int j = 0; j < 4; j++) {
            part0[base + j * 32] = ai[j];
            part1[base + j * 32] = af[j];
        }

        grid_barrier();

        if (tid < 128) {
            int p = blockIdx.x * 128 + tid;
            float ci = 0.f, cf = 0.f;
#pragma unroll
            for (int q = 0; q < 8; q++) {
                ci += __ldcg(&part0[q * BH + p]);
                cf += __ldcg(&part1[q * BH + p]);
            }
            int g = p >> 5, b = p & 31;
            int idx = b * HID + g;
            size_t sidx = (size_t)s * BH + idx;
            float ig = 1.f / (1.f + expf(-(ci + xi[sidx])));
            float fg = 1.f / (1.f + expf(-(cf + xf[sidx])));
            float nl = ig * xseq[sidx] + fg * __ldcg(latp + idx);
            lats[sidx] = nl;
            lats_h[sidx] = __float2half_rn(nl);
            if (s == S_LEN - 1 && igout) {
                igout[idx] = ig;
                fgout[idx] = fg;
            }
        }

        if (s != S_LEN - 1) grid_barrier();
    }
}

// ---------------- host orchestration ----------------
extern "C" void kernel_launch(void* const* d_in, const int* in_sizes, int n_in,
                              void* d_out, int out_size) {
    const int*   word    = (const int*)d_in[0];
    const float* latent0 = (const float*)d_in[1];
    const float* emb     = (const float*)d_in[2];
    const float* h2o_w   = (const float*)d_in[3];
    const float* h2o_b   = (const float*)d_in[4];
    const float* Whi     = (const float*)d_in[5];
    const float* Wxi_w   = (const float*)d_in[6];
    const float* Wxi_b   = (const float*)d_in[7];
    const float* Whf     = (const float*)d_in[8];
    const float* Wxf_w   = (const float*)d_in[9];
    const float* Wxf_b   = (const float*)d_in[10];
    const float* Whi2    = (const float*)d_in[11];
    const float* Wxi2_w  = (const float*)d_in[12];
    const float* Wxi2_b  = (const float*)d_in[13];
    const float* Whf2    = (const float*)d_in[14];
    const float* Wxf2_w  = (const float*)d_in[15];
    const float* Wxf2_b  = (const float*)d_in[16];
    float* out = (float*)d_out;

    float *embeds, *xi1, *xf1, *xi2, *xf2, *lats1, *lats2, *p0, *p1;
    __half *embeds_h, *lats1_h, *lats2_h, *h2o_h, *wx_h;
    cudaGetSymbolAddress((void**)&embeds, g_embeds);
    cudaGetSymbolAddress((void**)&embeds_h, g_embeds_h);
    cudaGetSymbolAddress((void**)&xi1, g_xi1);
    cudaGetSymbolAddress((void**)&xf1, g_xf1);
    cudaGetSymbolAddress((void**)&xi2, g_xi2);
    cudaGetSymbolAddress((void**)&xf2, g_xf2);
    cudaGetSymbolAddress((void**)&lats1, g_lats1);
    cudaGetSymbolAddress((void**)&lats1_h, g_lats1_h);
    cudaGetSymbolAddress((void**)&lats2, g_lats2);
    cudaGetSymbolAddress((void**)&lats2_h, g_lats2_h);
    cudaGetSymbolAddress((void**)&p0, g_part0);
    cudaGetSymbolAddress((void**)&p1, g_part1);
    cudaGetSymbolAddress((void**)&h2o_h, g_h2o_h);
    cudaGetSymbolAddress((void**)&wx_h, g_wx_h);

    const int SMEM_REC = 2 * 32 * 128 * 4 + 32 * 33 * 16;   // 49664 bytes
    static bool attr_done = false;
    if (!attr_done) {
        cudaFuncSetAttribute(ran_recurrence,
                             cudaFuncAttributeMaxDynamicSharedMemorySize, SMEM_REC);
        cudaFuncSetAttribute(gemm_f16_pipe,
                             cudaFuncAttributeMaxDynamicSharedMemorySize, GEMM_SMEM);
        attr_done = true;
    }

    // output layout (reference return order): latent | logits | ig_last | fg_last
    float* out_latent = out;
    float* out_logits = out + BH;
    float* out_ig     = out + (size_t)BH + (size_t)SB * VOCAB;
    float* out_fg     = out_ig + BH;

    __half* wxi_h  = wx_h;
    __half* wxf_h  = wx_h + (size_t)HID * EMB;
    __half* wxi2_h = wx_h + 2 * (size_t)HID * EMB;
    __half* wxf2_h = wx_h + 3 * (size_t)HID * EMB;

    // 0) fp16 pre-conversion of GEMM weights
    {
        int n4w = (int)((size_t)VOCAB * HID / 4);
        to_f16_kernel<<<(n4w + 255) / 256, 256>>>(h2o_w, h2o_h, n4w);
        int n4 = HID * EMB / 4;
        to_f16_kernel<<<(n4 + 255) / 256, 256>>>(Wxi_w, wxi_h, n4);
        to_f16_kernel<<<(n4 + 255) / 256, 256>>>(Wxf_w, wxf_h, n4);
        to_f16_kernel<<<(n4 + 255) / 256, 256>>>(Wxi2_w, wxi2_h, n4);
        to_f16_kernel<<<(n4 + 255) / 256, 256>>>(Wxf2_w, wxf2_h, n4);
    }

    // 1) embedding gather (fp32 + fp16 copies)
    embed_gather<<<SB, 256>>>(word, emb, embeds, embeds_h);

    // 2) layer-1 input gate pre-activations (fp16 mma.sync + ldmatrix)
    {
        dim3 grid(HID / 128, SB / 128);
        gemm_f16_pipe<<<grid, 256, GEMM_SMEM>>>(embeds_h, wxi_h, Wxi_b, xi1,
                                                SB, HID, EMB, 0);
        gemm_f16_pipe<<<grid, 256, GEMM_SMEM>>>(embeds_h, wxf_h, Wxf_b, xf1,
                                                SB, HID, EMB, 0);
    }

    // 3) layer-1 recurrence (persistent, exact fp32)
    ran_recurrence<<<NBLK, 256, SMEM_REC>>>(Whi, Whf, xi1, xf1, embeds, latent0,
                                            lats1, lats1_h, p0, p1, nullptr, nullptr);

    // 4) layer-2 input gate pre-activations (input = l1_out)
    {
        dim3 grid(HID / 128, SB / 128);
        gemm_f16_pipe<<<grid, 256, GEMM_SMEM>>>(lats1_h, wxi2_h, Wxi2_b, xi2,
                                                SB, HID, EMB, 0);
        gemm_f16_pipe<<<grid, 256, GEMM_SMEM>>>(lats1_h, wxf2_h, Wxf2_b, xf2,
                                                SB, HID, EMB, 0);
    }

    // 5) layer-2 recurrence (initial latent = layer-1 final latent)
    ran_recurrence<<<NBLK, 256, SMEM_REC>>>(Whi2, Whf2, xi2, xf2, lats1,
                                            lats1 + (size_t)(S_LEN - 1) * BH,
                                            lats2, lats2_h, p0, p1, out_ig, out_fg);

    // 6) final latent copy
    cudaMemcpyAsync(out_latent, lats2 + (size_t)(S_LEN - 1) * BH,
                    BH * sizeof(float), cudaMemcpyDeviceToDevice);

    // 7) logits = l2_out @ h2o_w^T + h2o_b  (fp16 mma.sync, m-fastest grid)
    {
        dim3 grid(SB / 128, VOCAB / 128);
        gemm_f16_pipe<<<grid, 256, GEMM_SMEM>>>(lats2_h, h2o_h, h2o_b, out_logits,
                                                SB, VOCAB, HID, 1);
    }

    (void)in_sizes; (void)n_in; (void)out_size;
}

// round 11
// speedup vs baseline: 1.4145x; 1.4145x over previous
#include <cuda_runtime.h>
#include <cuda_fp16.h>
#include <math.h>
#include <stdint.h>

// ---------------- problem constants ----------------
#define S_LEN 128
#define BATCH 32
#define HID   1024
#define EMB   1024
#define VOCAB 32000
#define SB    (S_LEN * BATCH)          // 4096
#define BH    (BATCH * HID)            // 32768
#define NBLK  256                      // persistent recurrence grid

// ---------------- scratch (device globals; no runtime alloc) ----------------
__device__ float  g_embeds[SB * EMB];      // [S*B, E] exact fp32
__device__ __half g_embeds_h[SB * EMB];    // fp16 copy, k-permuted (GEMM A)
__device__ float  g_xi1[SB * HID];
__device__ float  g_xf1[SB * HID];
__device__ float  g_xi2[SB * HID];
__device__ float  g_xf2[SB * HID];
__device__ float  g_lats1[SB * HID];       // layer-1 latent sequence (= l1_out)
__device__ __half g_lats1_h[SB * HID];     // k-permuted
__device__ float  g_lats2[SB * HID];       // layer-2 latent sequence (= l2_out)
__device__ __half g_lats2_h[SB * HID];     // k-permuted
__device__ float  g_part0[8 * BH];         // split-K partials, gate i
__device__ float  g_part1[8 * BH];         // split-K partials, gate f
__device__ __half g_h2o_h[(size_t)VOCAB * HID];   // fp16 weights, k-permuted
__device__ __half g_wx_h[4][HID * EMB];           // fp16 weights, k-permuted
__device__ unsigned int g_bar_count;
__device__ unsigned int g_bar_gen;

// k-permutation: within each 16-k block, new layout holds old indices
// [2t,2t+1,2t+8,2t+9] at positions 4t..4t+3. Invariant for dot products when
// applied to BOTH operands. Old half-pair p -> new half-pair:
__device__ __forceinline__ int kperm_pair(int p) {
    int blk = p >> 3, jj = p & 7;
    return blk * 8 + (jj < 4 ? 2 * jj : 2 * (jj - 4) + 1);
}

// ---------------- helpers ----------------
__device__ __forceinline__ void mma_f16(float c[4],
                                        uint32_t a0, uint32_t a1, uint32_t a2, uint32_t a3,
                                        uint32_t b0, uint32_t b1) {
    asm volatile(
        "mma.sync.aligned.m16n8k16.row.col.f32.f16.f16.f32 "
        "{%0,%1,%2,%3}, {%4,%5,%6,%7}, {%8,%9}, {%0,%1,%2,%3};"
        : "+f"(c[0]), "+f"(c[1]), "+f"(c[2]), "+f"(c[3])
        : "r"(a0), "r"(a1), "r"(a2), "r"(a3), "r"(b0), "r"(b1));
}

__device__ __forceinline__ void cp_async16(void* smem_dst, const void* gsrc) {
    uint32_t s = (uint32_t)__cvta_generic_to_shared(smem_dst);
    asm volatile("cp.async.cg.shared.global [%0], [%1], 16;" :: "r"(s), "l"(gsrc));
}

__device__ __forceinline__ void lds64(uint32_t& r0, uint32_t& r1, const void* p) {
    uint32_t a = (uint32_t)__cvta_generic_to_shared(p);
    asm volatile("ld.shared.v2.b32 {%0,%1}, [%2];" : "=r"(r0), "=r"(r1) : "r"(a));
}

// ---------------- fp16 conversion pre-pass (k-permuted output) ---------------
__global__ void to_f16_kernel(const float* __restrict__ src, __half* __restrict__ dst,
                              int n4) {
    int i = blockIdx.x * blockDim.x + threadIdx.x;
    if (i < n4) {
        float4 v = ((const float4*)src)[i];
        __half2* d2 = (__half2*)dst;
        d2[kperm_pair(2 * i)]     = __floats2half2_rn(v.x, v.y);
        d2[kperm_pair(2 * i + 1)] = __floats2half2_rn(v.z, v.w);
    }
}

// ---------------- embedding gather (fp32 + k-permuted fp16 copies) -----------
__global__ void embed_gather(const int* __restrict__ word,
                             const float* __restrict__ emb,
                             float* __restrict__ out,
                             __half* __restrict__ out_h) {
    int row = blockIdx.x;                 // 0..4095 = s*B+b
    int w = word[row];
    float4 v = ((const float4*)(emb + (size_t)w * EMB))[threadIdx.x];
    ((float4*)(out + (size_t)row * EMB))[threadIdx.x] = v;
    __half2* d2 = (__half2*)(out_h + (size_t)row * EMB);
    d2[kperm_pair(2 * threadIdx.x)]     = __floats2half2_rn(v.x, v.y);
    d2[kperm_pair(2 * threadIdx.x + 1)] = __floats2half2_rn(v.z, v.w);
}

// ---------------- pipelined fp16 NT GEMM: C = A[M,K]*B[N,K]^T + bias[N] ------
// A,B fp16 k-permuted, fp32 accum. BM=BN=128, BK=32, 3-stage cp.async,
// LDS.64 fragment loads + mma.sync m16n8k16. 8 warps (4m x 2n), warp 32x64.
#define PSTAGES 3
#define HSTRIDE 48                       // halves per tile row (32 data + 16 pad)
#define HTILE   (128 * HSTRIDE)          // 6144 halves per tile
#define GEMM_SMEM (PSTAGES * 2 * HTILE * 2)   // 73728 bytes

__global__ __launch_bounds__(256, 2)
void gemm_f16_pipe(const __half* __restrict__ A, const __half* __restrict__ B,
                   const float* __restrict__ bias, float* __restrict__ C,
                   int M, int N, int K, int swap) {
    extern __shared__ __half smh[];
    __half* As = smh;                      // [PSTAGES][128][HSTRIDE]
    __half* Bs = smh + PSTAGES * HTILE;

    int tid = threadIdx.x;
    int bn = (swap ? blockIdx.y : blockIdx.x) * 128;
    int bm = (swap ? blockIdx.x : blockIdx.y) * 128;
    int wid = tid >> 5, lane = tid & 31;
    int wm = wid & 3;
    int wn = wid >> 2;
    int grp = lane >> 2;
    int tig = lane & 3;

    // load mapping: tile = 128 rows x 32 halves = 512 16B-chunks; thread does 2
    int r0 = tid >> 2, c0 = (tid & 3) << 3;      // chunk tid
    int r1 = r0 + 64, c1 = c0;                   // chunk tid+256
    const __half* Ab = A + (size_t)bm * K;
    const __half* Bb = B + (size_t)bn * K;

    float acc[2][8][4];
#pragma unroll
    for (int i = 0; i < 2; i++)
#pragma unroll
        for (int j = 0; j < 8; j++)
#pragma unroll
            for (int q = 0; q < 4; q++) acc[i][j][q] = 0.f;

    int KT = K >> 5;

#pragma unroll
    for (int s = 0; s < PSTAGES - 1; s++) {
        int k0 = s * 32;
        cp_async16(&As[s * HTILE + r0 * HSTRIDE + c0], Ab + (size_t)r0 * K + k0 + c0);
        cp_async16(&As[s * HTILE + r1 * HSTRIDE + c1], Ab + (size_t)r1 * K + k0 + c1);
        cp_async16(&Bs[s * HTILE + r0 * HSTRIDE + c0], Bb + (size_t)r0 * K + k0 + c0);
        cp_async16(&Bs[s * HTILE + r1 * HSTRIDE + c1], Bb + (size_t)r1 * K + k0 + c1);
        asm volatile("cp.async.commit_group;");
    }

    for (int kt = 0; kt < KT; kt++) {
        asm volatile("cp.async.wait_group %0;" :: "n"(PSTAGES - 2));
        __syncthreads();

        const __half* Ast = &As[(kt % PSTAGES) * HTILE];
        const __half* Bst = &Bs[(kt % PSTAGES) * HTILE];

#pragma unroll
        for (int ks = 0; ks < 2; ks++) {
            int kb = ks * 16 + 4 * tig;   // permuted: 4 halves = old {2t,2t+1,2t+8,2t+9}
            uint32_t af[2][4];
#pragma unroll
            for (int i = 0; i < 2; i++) {
                int mr = wm * 32 + i * 16 + grp;
                lds64(af[i][0], af[i][2], &Ast[mr * HSTRIDE + kb]);
                lds64(af[i][1], af[i][3], &Ast[(mr + 8) * HSTRIDE + kb]);
            }
            uint32_t bf[8][2];
#pragma unroll
            for (int j = 0; j < 8; j++) {
                int nc = wn * 64 + j * 8 + grp;
                lds64(bf[j][0], bf[j][1], &Bst[nc * HSTRIDE + kb]);
            }
#pragma unroll
            for (int i = 0; i < 2; i++)
#pragma unroll
                for (int j = 0; j < 8; j++)
                    mma_f16(acc[i][j], af[i][0], af[i][1], af[i][2], af[i][3],
                            bf[j][0], bf[j][1]);
        }

        int nk = kt + PSTAGES - 1;
        if (nk < KT) {
            int st = nk % PSTAGES;
            int k0 = nk * 32;
            cp_async16(&As[st * HTILE + r0 * HSTRIDE + c0], Ab + (size_t)r0 * K + k0 + c0);
            cp_async16(&As[st * HTILE + r1 * HSTRIDE + c1], Ab + (size_t)r1 * K + k0 + c1);
            cp_async16(&Bs[st * HTILE + r0 * HSTRIDE + c0], Bb + (size_t)r0 * K + k0 + c0);
            cp_async16(&Bs[st * HTILE + r1 * HSTRIDE + c1], Bb + (size_t)r1 * K + k0 + c1);
        }
        asm volatile("cp.async.commit_group;");
    }

    // epilogue (fp32 accumulators + bias)
#pragma unroll
    for (int i = 0; i < 2; i++) {
        int row = bm + wm * 32 + i * 16 + grp;
#pragma unroll
        for (int j = 0; j < 8; j++) {
            int col = bn + wn * 64 + j * 8 + 2 * tig;
            float bsv0 = bias[col], bsv1 = bias[col + 1];
            float2 o0 = make_float2(acc[i][j][0] + bsv0, acc[i][j][1] + bsv1);
            float2 o1 = make_float2(acc[i][j][2] + bsv0, acc[i][j][3] + bsv1);
            *(float2*)(C + (size_t)row * N + col) = o0;
            *(float2*)(C + (size_t)(row + 8) * N + col) = o1;
        }
    }
}

// ---------------- software grid barrier (all NBLK blocks co-resident) --------
__device__ __forceinline__ void grid_barrier() {
    __syncthreads();
    if (threadIdx.x == 0) {
        volatile unsigned int* genp = &g_bar_gen;
        unsigned int gen = *genp;
        __threadfence();
        unsigned int rank = atomicAdd(&g_bar_count, 1u);
        if (rank == NBLK - 1) {
            g_bar_count = 0u;
            __threadfence();
            *genp = gen + 1u;
        } else {
            while (*genp == gen) { __nanosleep(32); }
        }
        __threadfence();
    }
    __syncthreads();
}

// ---------------- persistent recurrence (R4-proven): one launch per layer ----
__global__ __launch_bounds__(256)
void ran_recurrence(const float* __restrict__ Wi, const float* __restrict__ Wf,
                    const float* __restrict__ xi, const float* __restrict__ xf,
                    const float* __restrict__ xseq,
                    const float* __restrict__ lat0,
                    float* __restrict__ lats,
                    __half* __restrict__ lats_h,      // k-permuted fp16 copy
                    float* __restrict__ part0, float* __restrict__ part1,
                    float* __restrict__ igout, float* __restrict__ fgout) {
    extern __shared__ char smem_raw[];
    float (*sW)[32][128] = (float (*)[32][128])smem_raw;
    float4 (*sLat)[33] = (float4 (*)[33])(smem_raw + 2 * 32 * 128 * 4);

    int tid = threadIdx.x;
    int gt = blockIdx.x & 31;
    int kc = blockIdx.x >> 5;
    int g0 = gt * 32;
    int k0 = kc * 128;

    for (int i = tid; i < 2048; i += 256) {
        int mtx = i >> 10;
        int g = (i >> 5) & 31, kq = i & 31;
        const float* Wp = mtx ? Wf : Wi;
        *(float4*)&sW[mtx][g][kq * 4] =
            *(const float4*)(Wp + (size_t)(g0 + g) * HID + k0 + kq * 4);
    }

    int w = tid >> 5, lane = tid & 31;

    for (int s = 0; s < S_LEN; s++) {
        const float* latp = (s == 0) ? lat0 : (lats + (size_t)(s - 1) * BH);

        for (int i = tid; i < 1024; i += 256) {
            int b = i >> 5, kq = i & 31;
            const float4* src = (const float4*)(latp + b * HID + k0 + kq * 4);
            sLat[b][kq] = __ldcg(src);
        }
        __syncthreads();

        float ai[4] = {0.f, 0.f, 0.f, 0.f};
        float af[4] = {0.f, 0.f, 0.f, 0.f};
#pragma unroll 8
        for (int k4 = 0; k4 < 32; k4++) {
            float4 lv = sLat[lane][k4];
#pragma unroll
            for (int j = 0; j < 4; j++) {
                float4 wiv = *(const float4*)&sW[0][w * 4 + j][k4 * 4];
                float4 wfv = *(const float4*)&sW[1][w * 4 + j][k4 * 4];
                ai[j] += wiv.x * lv.x + wiv.y * lv.y + wiv.z * lv.z + wiv.w * lv.w;
                af[j] += wfv.x * lv.x + wfv.y * lv.y + wfv.z * lv.z + wfv.w * lv.w;
            }
        }
        int base = kc * BH + (g0 + w * 4) * 32 + lane;
#pragma unroll
        for (int j = 0; j < 4; j++) {
            part0[base + j * 32] = ai[j];
            part1[base + j * 32] = af[j];
        }

        grid_barrier();

        if (tid < 128) {
            int p = blockIdx.x * 128 + tid;
            float ci = 0.f, cf = 0.f;
#pragma unroll
            for (int q = 0; q < 8; q++) {
                ci += __ldcg(&part0[q * BH + p]);
                cf += __ldcg(&part1[q * BH + p]);
            }
            int g = p >> 5, b = p & 31;
            int idx = b * HID + g;
            size_t sidx = (size_t)s * BH + idx;
            float ig = 1.f / (1.f + expf(-(ci + xi[sidx])));
            float fg = 1.f / (1.f + expf(-(cf + xf[sidx])));
            float nl = ig * xseq[sidx] + fg * __ldcg(latp + idx);
            lats[sidx] = nl;
            // k-permuted fp16 shadow write (permute g within its 16-block)
            {
                int gp = kperm_pair(g >> 1) * 2 + (g & 1);
                lats_h[(size_t)s * BH + b * HID + gp] = __float2half_rn(nl);
            }
            if (s == S_LEN - 1 && igout) {
                igout[idx] = ig;
                fgout[idx] = fg;
            }
        }

        if (s != S_LEN - 1) grid_barrier();
    }
}

// ---------------- host orchestration ----------------
extern "C" void kernel_launch(void* const* d_in, const int* in_sizes, int n_in,
                              void* d_out, int out_size) {
    const int*   word    = (const int*)d_in[0];
    const float* latent0 = (const float*)d_in[1];
    const float* emb     = (const float*)d_in[2];
    const float* h2o_w   = (const float*)d_in[3];
    const float* h2o_b   = (const float*)d_in[4];
    const float* Whi     = (const float*)d_in[5];
    const float* Wxi_w   = (const float*)d_in[6];
    const float* Wxi_b   = (const float*)d_in[7];
    const float* Whf     = (const float*)d_in[8];
    const float* Wxf_w   = (const float*)d_in[9];
    const float* Wxf_b   = (const float*)d_in[10];
    const float* Whi2    = (const float*)d_in[11];
    const float* Wxi2_w  = (const float*)d_in[12];
    const float* Wxi2_b  = (const float*)d_in[13];
    const float* Whf2    = (const float*)d_in[14];
    const float* Wxf2_w  = (const float*)d_in[15];
    const float* Wxf2_b  = (const float*)d_in[16];
    float* out = (float*)d_out;

    float *embeds, *xi1, *xf1, *xi2, *xf2, *lats1, *lats2, *p0, *p1;
    __half *embeds_h, *lats1_h, *lats2_h, *h2o_h, *wx_h;
    cudaGetSymbolAddress((void**)&embeds, g_embeds);
    cudaGetSymbolAddress((void**)&embeds_h, g_embeds_h);
    cudaGetSymbolAddress((void**)&xi1, g_xi1);
    cudaGetSymbolAddress((void**)&xf1, g_xf1);
    cudaGetSymbolAddress((void**)&xi2, g_xi2);
    cudaGetSymbolAddress((void**)&xf2, g_xf2);
    cudaGetSymbolAddress((void**)&lats1, g_lats1);
    cudaGetSymbolAddress((void**)&lats1_h, g_lats1_h);
    cudaGetSymbolAddress((void**)&lats2, g_lats2);
    cudaGetSymbolAddress((void**)&lats2_h, g_lats2_h);
    cudaGetSymbolAddress((void**)&p0, g_part0);
    cudaGetSymbolAddress((void**)&p1, g_part1);
    cudaGetSymbolAddress((void**)&h2o_h, g_h2o_h);
    cudaGetSymbolAddress((void**)&wx_h, g_wx_h);

    const int SMEM_REC = 2 * 32 * 128 * 4 + 32 * 33 * 16;   // 49664 bytes
    static bool attr_done = false;
    if (!attr_done) {
        cudaFuncSetAttribute(ran_recurrence,
                             cudaFuncAttributeMaxDynamicSharedMemorySize, SMEM_REC);
        cudaFuncSetAttribute(gemm_f16_pipe,
                             cudaFuncAttributeMaxDynamicSharedMemorySize, GEMM_SMEM);
        attr_done = true;
    }

    // output layout (reference return order): latent | logits | ig_last | fg_last
    float* out_latent = out;
    float* out_logits = out + BH;
    float* out_ig     = out + (size_t)BH + (size_t)SB * VOCAB;
    float* out_fg     = out_ig + BH;

    __half* wxi_h  = wx_h;
    __half* wxf_h  = wx_h + (size_t)HID * EMB;
    __half* wxi2_h = wx_h + 2 * (size_t)HID * EMB;
    __half* wxf2_h = wx_h + 3 * (size_t)HID * EMB;

    // 0) fp16 pre-conversion of GEMM weights (k-permuted)
    {
        int n4w = (int)((size_t)VOCAB * HID / 4);
        to_f16_kernel<<<(n4w + 255) / 256, 256>>>(h2o_w, h2o_h, n4w);
        int n4 = HID * EMB / 4;
        to_f16_kernel<<<(n4 + 255) / 256, 256>>>(Wxi_w, wxi_h, n4);
        to_f16_kernel<<<(n4 + 255) / 256, 256>>>(Wxf_w, wxf_h, n4);
        to_f16_kernel<<<(n4 + 255) / 256, 256>>>(Wxi2_w, wxi2_h, n4);
        to_f16_kernel<<<(n4 + 255) / 256, 256>>>(Wxf2_w, wxf2_h, n4);
    }

    // 1) embedding gather (fp32 + k-permuted fp16 copies)
    embed_gather<<<SB, 256>>>(word, emb, embeds, embeds_h);

    // 2) layer-1 input gate pre-activations (fp16 mma.sync)
    {
        dim3 grid(HID / 128, SB / 128);
        gemm_f16_pipe<<<grid, 256, GEMM_SMEM>>>(embeds_h, wxi_h, Wxi_b, xi1,
                                                SB, HID, EMB, 0);
        gemm_f16_pipe<<<grid, 256, GEMM_SMEM>>>(embeds_h, wxf_h, Wxf_b, xf1,
                                                SB, HID, EMB, 0);
    }

    // 3) layer-1 recurrence (persistent, exact fp32)
    ran_recurrence<<<NBLK, 256, SMEM_REC>>>(Whi, Whf, xi1, xf1, embeds, latent0,
                                            lats1, lats1_h, p0, p1, nullptr, nullptr);

    // 4) layer-2 input gate pre-activations (input = l1_out)
    {
        dim3 grid(HID / 128, SB / 128);
        gemm_f16_pipe<<<grid, 256, GEMM_SMEM>>>(lats1_h, wxi2_h, Wxi2_b, xi2,
                                                SB, HID, EMB, 0);
        gemm_f16_pipe<<<grid, 256, GEMM_SMEM>>>(lats1_h, wxf2_h, Wxf2_b, xf2,
                                                SB, HID, EMB, 0);
    }

    // 5) layer-2 recurrence (initial latent = layer-1 final latent)
    ran_recurrence<<<NBLK, 256, SMEM_REC>>>(Whi2, Whf2, xi2, xf2, lats1,
                                            lats1 + (size_t)(S_LEN - 1) * BH,
                                            lats2, lats2_h, p0, p1, out_ig, out_fg);

    // 6) final latent copy
    cudaMemcpyAsync(out_latent, lats2 + (size_t)(S_LEN - 1) * BH,
                    BH * sizeof(float), cudaMemcpyDeviceToDevice);

    // 7) logits = l2_out @ h2o_w^T + h2o_b  (fp16 mma.sync, m-fastest grid)
    {
        dim3 grid(SB / 128, VOCAB / 128);
        gemm_f16_pipe<<<grid, 256, GEMM_SMEM>>>(lats2_h, h2o_h, h2o_b, out_logits,
                                                SB, VOCAB, HID, 1);
    }

    (void)in_sizes; (void)n_in; (void)out_size;
}

// round 12
// speedup vs baseline: 1.8579x; 1.3135x over previous
#include <cuda_runtime.h>
#include <cuda_fp16.h>
#include <math.h>
#include <stdint.h>

// ---------------- problem constants ----------------
#define S_LEN 128
#define BATCH 32
#define HID   1024
#define EMB   1024
#define VOCAB 32000
#define SB    (S_LEN * BATCH)          // 4096
#define BH    (BATCH * HID)            // 32768
#define NBLK  256                      // persistent recurrence grid

// ---------------- scratch (device globals; no runtime alloc) ----------------
__device__ float  g_embeds[SB * EMB];      // [S*B, E] exact fp32
__device__ __half g_embeds_h[SB * EMB];    // fp16 copy (GEMM A operand)
__device__ float  g_xi1[SB * HID];
__device__ float  g_xf1[SB * HID];
__device__ float  g_xi2[SB * HID];
__device__ float  g_xf2[SB * HID];
__device__ float  g_lats1[SB * HID];       // layer-1 latent sequence (= l1_out)
__device__ __half g_lats1_h[SB * HID];
__device__ float  g_lats2[SB * HID];       // layer-2 latent sequence (= l2_out)
__device__ __half g_lats2_h[SB * HID];
__device__ float  g_part0[8 * BH];         // split-K partials, gate i
__device__ float  g_part1[8 * BH];         // split-K partials, gate f
__device__ __half g_h2o_h[(size_t)VOCAB * HID];   // 64MB fp16 weight copy
__device__ __half g_wx_h[4][HID * EMB];           // fp16 copies of Wxi,Wxf,Wxi2,Wxf2
__device__ unsigned int g_bar_count;
__device__ unsigned int g_bar_gen;

// ---------------- helpers ----------------
__device__ __forceinline__ void mma_f16(float c[4],
                                        uint32_t a0, uint32_t a1, uint32_t a2, uint32_t a3,
                                        uint32_t b0, uint32_t b1) {
    asm volatile(
        "mma.sync.aligned.m16n8k16.row.col.f32.f16.f16.f32 "
        "{%0,%1,%2,%3}, {%4,%5,%6,%7}, {%8,%9}, {%0,%1,%2,%3};"
        : "+f"(c[0]), "+f"(c[1]), "+f"(c[2]), "+f"(c[3])
        : "r"(a0), "r"(a1), "r"(a2), "r"(a3), "r"(b0), "r"(b1));
}

__device__ __forceinline__ void cp_async16(void* smem_dst, const void* gsrc) {
    uint32_t s = (uint32_t)__cvta_generic_to_shared(smem_dst);
    asm volatile("cp.async.cg.shared.global [%0], [%1], 16;" :: "r"(s), "l"(gsrc));
}

// ---------------- fp16 conversion pre-pass ----------------
__global__ void to_f16_kernel(const float* __restrict__ src, __half* __restrict__ dst,
                              int n4) {
    int i = blockIdx.x * blockDim.x + threadIdx.x;
    if (i < n4) {
        float4 v = ((const float4*)src)[i];
        __half2* d = (__half2*)(dst + (size_t)i * 4);
        d[0] = __floats2half2_rn(v.x, v.y);
        d[1] = __floats2half2_rn(v.z, v.w);
    }
}

// ---------------- embedding gather (writes fp32 + fp16 copies) ----------------
__global__ void embed_gather(const int* __restrict__ word,
                             const float* __restrict__ emb,
                             float* __restrict__ out,
                             __half* __restrict__ out_h) {
    int row = blockIdx.x;                 // 0..4095 = s*B+b
    int w = word[row];
    float4 v = ((const float4*)(emb + (size_t)w * EMB))[threadIdx.x];
    ((float4*)(out + (size_t)row * EMB))[threadIdx.x] = v;
    __half2* d = (__half2*)(out_h + (size_t)row * EMB + (size_t)threadIdx.x * 4);
    d[0] = __floats2half2_rn(v.x, v.y);
    d[1] = __floats2half2_rn(v.z, v.w);
}

// ---------------- pipelined fp16 NT GEMM (R9-proven): C = A*B^T + bias -------
#define PSTAGES 3
#define HSTRIDE 40                       // halves per tile row (32 data + 8 pad)
#define HTILE   (128 * HSTRIDE)          // 5120 halves per tile
#define GEMM_SMEM (PSTAGES * 2 * HTILE * 2)   // 61440 bytes

__global__ __launch_bounds__(256, 2)
void gemm_f16_pipe(const __half* __restrict__ A, const __half* __restrict__ B,
                   const float* __restrict__ bias, float* __restrict__ C,
                   int M, int N, int K, int swap) {
    extern __shared__ __half smh[];
    __half* As = smh;                      // [PSTAGES][128][HSTRIDE]
    __half* Bs = smh + PSTAGES * HTILE;

    int tid = threadIdx.x;
    int bn = (swap ? blockIdx.y : blockIdx.x) * 128;
    int bm = (swap ? blockIdx.x : blockIdx.y) * 128;
    int wid = tid >> 5, lane = tid & 31;
    int wm = wid & 3;
    int wn = wid >> 2;
    int grp = lane >> 2;
    int tig = lane & 3;

    int r0 = tid >> 2, c0 = (tid & 3) << 3;      // chunk tid
    int r1 = r0 + 64, c1 = c0;                   // chunk tid+256
    const __half* Ab = A + (size_t)bm * K;
    const __half* Bb = B + (size_t)bn * K;

    float acc[2][8][4];
#pragma unroll
    for (int i = 0; i < 2; i++)
#pragma unroll
        for (int j = 0; j < 8; j++)
#pragma unroll
            for (int q = 0; q < 4; q++) acc[i][j][q] = 0.f;

    int KT = K >> 5;

#pragma unroll
    for (int s = 0; s < PSTAGES - 1; s++) {
        int k0 = s * 32;
        cp_async16(&As[s * HTILE + r0 * HSTRIDE + c0], Ab + (size_t)r0 * K + k0 + c0);
        cp_async16(&As[s * HTILE + r1 * HSTRIDE + c1], Ab + (size_t)r1 * K + k0 + c1);
        cp_async16(&Bs[s * HTILE + r0 * HSTRIDE + c0], Bb + (size_t)r0 * K + k0 + c0);
        cp_async16(&Bs[s * HTILE + r1 * HSTRIDE + c1], Bb + (size_t)r1 * K + k0 + c1);
        asm volatile("cp.async.commit_group;");
    }

    for (int kt = 0; kt < KT; kt++) {
        asm volatile("cp.async.wait_group %0;" :: "n"(PSTAGES - 2));
        __syncthreads();

        const __half* Ast = &As[(kt % PSTAGES) * HTILE];
        const __half* Bst = &Bs[(kt % PSTAGES) * HTILE];

#pragma unroll
        for (int ks = 0; ks < 2; ks++) {
            int koff = ks * 16 + 2 * tig;
            uint32_t af[2][4];
#pragma unroll
            for (int i = 0; i < 2; i++) {
                int mr = wm * 32 + i * 16 + grp;
                af[i][0] = *(const uint32_t*)&Ast[mr * HSTRIDE + koff];
                af[i][1] = *(const uint32_t*)&Ast[(mr + 8) * HSTRIDE + koff];
                af[i][2] = *(const uint32_t*)&Ast[mr * HSTRIDE + koff + 8];
                af[i][3] = *(const uint32_t*)&Ast[(mr + 8) * HSTRIDE + koff + 8];
            }
            uint32_t bf[8][2];
#pragma unroll
            for (int j = 0; j < 8; j++) {
                int nc = wn * 64 + j * 8 + grp;
                bf[j][0] = *(const uint32_t*)&Bst[nc * HSTRIDE + koff];
                bf[j][1] = *(const uint32_t*)&Bst[nc * HSTRIDE + koff + 8];
            }
#pragma unroll
            for (int i = 0; i < 2; i++)
#pragma unroll
                for (int j = 0; j < 8; j++)
                    mma_f16(acc[i][j], af[i][0], af[i][1], af[i][2], af[i][3],
                            bf[j][0], bf[j][1]);
        }

        int nk = kt + PSTAGES - 1;
        if (nk < KT) {
            int st = nk % PSTAGES;
            int k0 = nk * 32;
            cp_async16(&As[st * HTILE + r0 * HSTRIDE + c0], Ab + (size_t)r0 * K + k0 + c0);
            cp_async16(&As[st * HTILE + r1 * HSTRIDE + c1], Ab + (size_t)r1 * K + k0 + c1);
            cp_async16(&Bs[st * HTILE + r0 * HSTRIDE + c0], Bb + (size_t)r0 * K + k0 + c0);
            cp_async16(&Bs[st * HTILE + r1 * HSTRIDE + c1], Bb + (size_t)r1 * K + k0 + c1);
        }
        asm volatile("cp.async.commit_group;");
    }

#pragma unroll
    for (int i = 0; i < 2; i++) {
        int row = bm + wm * 32 + i * 16 + grp;
#pragma unroll
        for (int j = 0; j < 8; j++) {
            int col = bn + wn * 64 + j * 8 + 2 * tig;
            float bsv0 = bias[col], bsv1 = bias[col + 1];
            float2 o0 = make_float2(acc[i][j][0] + bsv0, acc[i][j][1] + bsv1);
            float2 o1 = make_float2(acc[i][j][2] + bsv0, acc[i][j][3] + bsv1);
            *(float2*)(C + (size_t)row * N + col) = o0;
            *(float2*)(C + (size_t)(row + 8) * N + col) = o1;
        }
    }
}

// ---------------- software grid barrier (all NBLK blocks co-resident) --------
__device__ __forceinline__ void grid_barrier() {
    __syncthreads();
    if (threadIdx.x == 0) {
        volatile unsigned int* genp = &g_bar_gen;
        unsigned int gen = *genp;
        __threadfence();
        unsigned int rank = atomicAdd(&g_bar_count, 1u);
        if (rank == NBLK - 1) {
            g_bar_count = 0u;
            __threadfence();
            *genp = gen + 1u;
        } else {
            while (*genp == gen) { __nanosleep(32); }
        }
        __threadfence();
    }
    __syncthreads();
}

// ---------------- persistent recurrence v3: tensorized gate GEMM -------------
// Same skeleton as R4 (256 blocks = 32 gt x 8 kc, 2 grid barriers/step, global
// partials + epilogue). Compute phase replaced by fp16-split (Markidis) HMMA:
// W = Whi + Wlo, lat = Lhi + Llo; preact = hi*hi + lo*hi + hi*lo (fp32 accum)
// -> fp32-class precision. Block tile: M=64 (32 i-rows + 32 f-rows), N=32, K=128.
#define RW 136                            // smem row stride (halves)
#define REC3_SMEM ((64 * RW + 64 * RW + 32 * RW + 32 * RW) * 2)   // 52224 B

__global__ __launch_bounds__(256)
void ran_recurrence3(const float* __restrict__ Wi, const float* __restrict__ Wf,
                     const float* __restrict__ xi, const float* __restrict__ xf,
                     const float* __restrict__ xseq,
                     const float* __restrict__ lat0,
                     float* __restrict__ lats,
                     __half* __restrict__ lats_h,
                     float* __restrict__ part0, float* __restrict__ part1,
                     float* __restrict__ igout, float* __restrict__ fgout) {
    extern __shared__ __half sh[];
    __half* sWhi = sh;                    // [64][RW]
    __half* sWlo = sh + 64 * RW;          // [64][RW]
    __half* sLhi = sh + 128 * RW;         // [32][RW]
    __half* sLlo = sh + 160 * RW;         // [32][RW]

    int tid = threadIdx.x;
    int gt = blockIdx.x & 31;
    int kc = blockIdx.x >> 5;
    int g0 = gt * 32;
    int k0 = kc * 128;
    int wid = tid >> 5, lane = tid & 31;
    int wm = wid & 3, wn = wid >> 2;
    int grp = lane >> 2, tig = lane & 3;

    // ---- load + split W once: 64 rows (32 gate-i + 32 gate-f) x 128 k ----
    for (int i = tid; i < 2048; i += 256) {         // 2048 float4 chunks
        int row = i >> 5, c4 = i & 31;
        const float* src = (row < 32)
            ? (Wi + (size_t)(g0 + row) * HID + k0 + c4 * 4)
            : (Wf + (size_t)(g0 + row - 32) * HID + k0 + c4 * 4);
        float4 v = *(const float4*)src;
        __half2 h0 = __floats2half2_rn(v.x, v.y);
        __half2 h1 = __floats2half2_rn(v.z, v.w);
        float2 f0 = __half22float2(h0), f1 = __half22float2(h1);
        __half2 l0 = __floats2half2_rn(v.x - f0.x, v.y - f0.y);
        __half2 l1 = __floats2half2_rn(v.z - f1.x, v.w - f1.y);
        int off = row * RW + c4 * 4;
        *(__half2*)&sWhi[off] = h0; *(__half2*)&sWhi[off + 2] = h1;
        *(__half2*)&sWlo[off] = l0; *(__half2*)&sWlo[off + 2] = l1;
    }

    const __half* Ahi = sWhi + (16 * wm + grp) * RW;
    const __half* Alo = sWlo + (16 * wm + grp) * RW;

    for (int s = 0; s < S_LEN; s++) {
        const float* latp = (s == 0) ? lat0 : (lats + (size_t)(s - 1) * BH);

        // ---- stage + split lat tile [32 b][128 k] ----
        for (int i = tid; i < 1024; i += 256) {
            int b = i >> 5, kq = i & 31;
            float4 v = __ldcg((const float4*)(latp + (size_t)b * HID + k0 + kq * 4));
            __half2 h0 = __floats2half2_rn(v.x, v.y);
            __half2 h1 = __floats2half2_rn(v.z, v.w);
            float2 f0 = __half22float2(h0), f1 = __half22float2(h1);
            __half2 l0 = __floats2half2_rn(v.x - f0.x, v.y - f0.y);
            __half2 l1 = __floats2half2_rn(v.z - f1.x, v.w - f1.y);
            int off = b * RW + kq * 4;
            *(__half2*)&sLhi[off] = h0; *(__half2*)&sLhi[off + 2] = h1;
            *(__half2*)&sLlo[off] = l0; *(__half2*)&sLlo[off + 2] = l1;
        }
        __syncthreads();

        // ---- split-K gate GEMM via HMMA: warp tile m16 x n16 (2 n-tiles) ----
        float acc[2][4];
#pragma unroll
        for (int jj = 0; jj < 2; jj++)
#pragma unroll
            for (int q = 0; q < 4; q++) acc[jj][q] = 0.f;

#pragma unroll
        for (int ks = 0; ks < 8; ks++) {
            int kb = ks * 16 + 2 * tig;
            uint32_t ah0 = *(const uint32_t*)&Ahi[kb];
            uint32_t ah1 = *(const uint32_t*)&Ahi[8 * RW + kb];
            uint32_t ah2 = *(const uint32_t*)&Ahi[kb + 8];
            uint32_t ah3 = *(const uint32_t*)&Ahi[8 * RW + kb + 8];
            uint32_t al0 = *(const uint32_t*)&Alo[kb];
            uint32_t al1 = *(const uint32_t*)&Alo[8 * RW + kb];
            uint32_t al2 = *(const uint32_t*)&Alo[kb + 8];
            uint32_t al3 = *(const uint32_t*)&Alo[8 * RW + kb + 8];
#pragma unroll
            for (int jj = 0; jj < 2; jj++) {
                int brow = (16 * wn + 8 * jj + grp) * RW;
                uint32_t bh0 = *(const uint32_t*)&sLhi[brow + kb];
                uint32_t bh1 = *(const uint32_t*)&sLhi[brow + kb + 8];
                uint32_t bl0 = *(const uint32_t*)&sLlo[brow + kb];
                uint32_t bl1 = *(const uint32_t*)&sLlo[brow + kb + 8];
                mma_f16(acc[jj], ah0, ah1, ah2, ah3, bh0, bh1);   // hi*hi
                mma_f16(acc[jj], al0, al1, al2, al3, bh0, bh1);   // lo*hi
                mma_f16(acc[jj], ah0, ah1, ah2, ah3, bl0, bl1);   // hi*lo
            }
        }

        // ---- write partials (same [kc][g*32+b] layout as R4) ----
        int row0 = 16 * wm + grp;
#pragma unroll
        for (int jj = 0; jj < 2; jj++) {
            int bcol = 16 * wn + 8 * jj + 2 * tig;
            {
                int r = row0;
                float* pp = (r < 32) ? part0 : part1;
                int gg = g0 + (r & 31);
                pp[kc * BH + gg * 32 + bcol]     = acc[jj][0];
                pp[kc * BH + gg * 32 + bcol + 1] = acc[jj][1];
            }
            {
                int r = row0 + 8;
                float* pp = (r < 32) ? part0 : part1;
                int gg = g0 + (r & 31);
                pp[kc * BH + gg * 32 + bcol]     = acc[jj][2];
                pp[kc * BH + gg * 32 + bcol + 1] = acc[jj][3];
            }
        }

        grid_barrier();

        // ---- epilogue: reduce + sigmoid + state update (R4-proven) ----
        if (tid < 128) {
            int p = blockIdx.x * 128 + tid;
            float ci = 0.f, cf = 0.f;
#pragma unroll
            for (int q = 0; q < 8; q++) {
                ci += __ldcg(&part0[q * BH + p]);
                cf += __ldcg(&part1[q * BH + p]);
            }
            int g = p >> 5, b = p & 31;
            int idx = b * HID + g;
            size_t sidx = (size_t)s * BH + idx;
            float ig = 1.f / (1.f + expf(-(ci + xi[sidx])));
            float fg = 1.f / (1.f + expf(-(cf + xf[sidx])));
            float nl = ig * xseq[sidx] + fg * __ldcg(latp + idx);
            lats[sidx] = nl;
            lats_h[sidx] = __float2half_rn(nl);
            if (s == S_LEN - 1 && igout) {
                igout[idx] = ig;
                fgout[idx] = fg;
            }
        }

        if (s != S_LEN - 1) grid_barrier();
    }
}

// ---------------- host orchestration ----------------
extern "C" void kernel_launch(void* const* d_in, const int* in_sizes, int n_in,
                              void* d_out, int out_size) {
    const int*   word    = (const int*)d_in[0];
    const float* latent0 = (const float*)d_in[1];
    const float* emb     = (const float*)d_in[2];
    const float* h2o_w   = (const float*)d_in[3];
    const float* h2o_b   = (const float*)d_in[4];
    const float* Whi     = (const float*)d_in[5];
    const float* Wxi_w   = (const float*)d_in[6];
    const float* Wxi_b   = (const float*)d_in[7];
    const float* Whf     = (const float*)d_in[8];
    const float* Wxf_w   = (const float*)d_in[9];
    const float* Wxf_b   = (const float*)d_in[10];
    const float* Whi2    = (const float*)d_in[11];
    const float* Wxi2_w  = (const float*)d_in[12];
    const float* Wxi2_b  = (const float*)d_in[13];
    const float* Whf2    = (const float*)d_in[14];
    const float* Wxf2_w  = (const float*)d_in[15];
    const float* Wxf2_b  = (const float*)d_in[16];
    float* out = (float*)d_out;

    float *embeds, *xi1, *xf1, *xi2, *xf2, *lats1, *lats2, *p0, *p1;
    __half *embeds_h, *lats1_h, *lats2_h, *h2o_h, *wx_h;
    cudaGetSymbolAddress((void**)&embeds, g_embeds);
    cudaGetSymbolAddress((void**)&embeds_h, g_embeds_h);
    cudaGetSymbolAddress((void**)&xi1, g_xi1);
    cudaGetSymbolAddress((void**)&xf1, g_xf1);
    cudaGetSymbolAddress((void**)&xi2, g_xi2);
    cudaGetSymbolAddress((void**)&xf2, g_xf2);
    cudaGetSymbolAddress((void**)&lats1, g_lats1);
    cudaGetSymbolAddress((void**)&lats1_h, g_lats1_h);
    cudaGetSymbolAddress((void**)&lats2, g_lats2);
    cudaGetSymbolAddress((void**)&lats2_h, g_lats2_h);
    cudaGetSymbolAddress((void**)&p0, g_part0);
    cudaGetSymbolAddress((void**)&p1, g_part1);
    cudaGetSymbolAddress((void**)&h2o_h, g_h2o_h);
    cudaGetSymbolAddress((void**)&wx_h, g_wx_h);

    static bool attr_done = false;
    if (!attr_done) {
        cudaFuncSetAttribute(ran_recurrence3,
                             cudaFuncAttributeMaxDynamicSharedMemorySize, REC3_SMEM);
        cudaFuncSetAttribute(gemm_f16_pipe,
                             cudaFuncAttributeMaxDynamicSharedMemorySize, GEMM_SMEM);
        attr_done = true;
    }

    // output layout (reference return order): latent | logits | ig_last | fg_last
    float* out_latent = out;
    float* out_logits = out + BH;
    float* out_ig     = out + (size_t)BH + (size_t)SB * VOCAB;
    float* out_fg     = out_ig + BH;

    __half* wxi_h  = wx_h;
    __half* wxf_h  = wx_h + (size_t)HID * EMB;
    __half* wxi2_h = wx_h + 2 * (size_t)HID * EMB;
    __half* wxf2_h = wx_h + 3 * (size_t)HID * EMB;

    // 0) fp16 pre-conversion of batched-GEMM weights
    {
        int n4w = (int)((size_t)VOCAB * HID / 4);
        to_f16_kernel<<<(n4w + 255) / 256, 256>>>(h2o_w, h2o_h, n4w);
        int n4 = HID * EMB / 4;
        to_f16_kernel<<<(n4 + 255) / 256, 256>>>(Wxi_w, wxi_h, n4);
        to_f16_kernel<<<(n4 + 255) / 256, 256>>>(Wxf_w, wxf_h, n4);
        to_f16_kernel<<<(n4 + 255) / 256, 256>>>(Wxi2_w, wxi2_h, n4);
        to_f16_kernel<<<(n4 + 255) / 256, 256>>>(Wxf2_w, wxf2_h, n4);
    }

    // 1) embedding gather (fp32 + fp16 copies)
    embed_gather<<<SB, 256>>>(word, emb, embeds, embeds_h);

    // 2) layer-1 input gate pre-activations (fp16 mma.sync)
    {
        dim3 grid(HID / 128, SB / 128);
        gemm_f16_pipe<<<grid, 256, GEMM_SMEM>>>(embeds_h, wxi_h, Wxi_b, xi1,
                                                SB, HID, EMB, 0);
        gemm_f16_pipe<<<grid, 256, GEMM_SMEM>>>(embeds_h, wxf_h, Wxf_b, xf1,
                                                SB, HID, EMB, 0);
    }

    // 3) layer-1 recurrence (persistent, fp16-split HMMA, fp32-class precision)
    ran_recurrence3<<<NBLK, 256, REC3_SMEM>>>(Whi, Whf, xi1, xf1, embeds, latent0,
                                              lats1, lats1_h, p0, p1,
                                              nullptr, nullptr);

    // 4) layer-2 input gate pre-activations (input = l1_out)
    {
        dim3 grid(HID / 128, SB / 128);
        gemm_f16_pipe<<<grid, 256, GEMM_SMEM>>>(lats1_h, wxi2_h, Wxi2_b, xi2,
                                                SB, HID, EMB, 0);
        gemm_f16_pipe<<<grid, 256, GEMM_SMEM>>>(lats1_h, wxf2_h, Wxf2_b, xf2,
                                                SB, HID, EMB, 0);
    }

    // 5) layer-2 recurrence (initial latent = layer-1 final latent)
    ran_recurrence3<<<NBLK, 256, REC3_SMEM>>>(Whi2, Whf2, xi2, xf2, lats1,
                                              lats1 + (size_t)(S_LEN - 1) * BH,
                                              lats2, lats2_h, p0, p1,
                                              out_ig, out_fg);

    // 6) final latent copy
    cudaMemcpyAsync(out_latent, lats2 + (size_t)(S_LEN - 1) * BH,
                    BH * sizeof(float), cudaMemcpyDeviceToDevice);

    // 7) logits = l2_out @ h2o_w^T + h2o_b  (fp16 mma.sync, m-fastest grid)
    {
        dim3 grid(SB / 128, VOCAB / 128);
        gemm_f16_pipe<<<grid, 256, GEMM_SMEM>>>(lats2_h, h2o_h, h2o_b, out_logits,
                                                SB, VOCAB, HID, 1);
    }

    (void)in_sizes; (void)n_in; (void)out_size;
}